// round 13
// baseline (speedup 1.0000x reference)
#include <cuda_runtime.h>
#include <cuda_fp16.h>
#include <math.h>
#include <stdint.h>

// Shapes (fixed by the problem)
#define NB   16
#define CCH  256
#define HH   32
#define WW   32
#define LL   (HH*WW)       // 1024
#define PP   2048
#define KEEP 102           // int(0.05 * 2048)
#define K3   768           // 3x fp16 split K (h | l*64 | h/64) . (h | h/64 | l*64)

// ---------------------------------------------------------------------------
// Scratch (device globals only; no allocations allowed)
// ---------------------------------------------------------------------------
__device__ float  g_invxn[NB * LL];                    // 64 KB
__device__ __half g_A[(size_t)NB * LL * K3];           // 25 MB  A' split of x^T * invxn
__device__ __half g_B[(size_t)PP * K3];                // 3 MB   B' split of poolN
__device__ float  g_cos[(size_t)NB * LL * PP];         // 134 MB

// ---------------------------------------------------------------------------
// Kernel 1: normalize pool rows, write fp16 split B' = [h | h/64 | l*64]
// ---------------------------------------------------------------------------
__global__ void prep_pool(const float* __restrict__ pool) {
    int p = blockIdx.x;
    int c = threadIdx.x;
    float v = pool[p * CCH + c];
    __shared__ float red[256];
    red[c] = v * v;
    __syncthreads();
    #pragma unroll
    for (int s = 128; s > 0; s >>= 1) {
        if (c < s) red[c] += red[c + s];
        __syncthreads();
    }
    float vn = v * (1.0f / sqrtf(red[0]));
    __half h  = __float2half(vn);
    float  hf = __half2float(h);
    __half l  = __float2half((vn - hf) * 64.0f);     // scaled residual (normal range)
    __half hs = __float2half(hf * 0.015625f);        // h / 64 (exact pow2 scale)
    __half* dst = g_B + (size_t)p * K3 + c;
    dst[0]   = h;
    dst[256] = hs;
    dst[512] = l;
}

// ---------------------------------------------------------------------------
// Kernel 2: per-pixel inverse norm of x.
// ---------------------------------------------------------------------------
__global__ void prep_xnorm(const float* __restrict__ x) {
    int idx = blockIdx.x * 256 + threadIdx.x;   // 0 .. 16383
    int n = idx >> 10, l = idx & (LL - 1);
    const float* xp = x + (size_t)n * CCH * LL + l;
    float s = 0.f;
    #pragma unroll 8
    for (int c = 0; c < CCH; c++) {
        float v = xp[c * LL];
        s = fmaf(v, v, s);
    }
    g_invxn[idx] = 1.0f / sqrtf(s);
}

// ---------------------------------------------------------------------------
// Kernel 3: transpose x [n][c][l] -> A' [n][l][K3] fp16 split [h | l*64 | h/64],
// with invxn folded in. 32x32 tiles, 256 threads.
// ---------------------------------------------------------------------------
__global__ __launch_bounds__(256) void prep_xT(const float* __restrict__ x) {
    int n  = blockIdx.z;
    int c0 = blockIdx.y * 32;
    int l0 = blockIdx.x * 32;
    int tx = threadIdx.x & 31;
    int ty = threadIdx.x >> 5;     // 0..7
    __shared__ float ss[32][33];

    const float* xp = x + (size_t)n * CCH * LL;
    #pragma unroll
    for (int i = 0; i < 4; i++) {
        int c = ty * 4 + i;
        ss[c][tx] = xp[(size_t)(c0 + c) * LL + l0 + tx];
    }
    __syncthreads();
    #pragma unroll
    for (int i = 0; i < 4; i++) {
        int lloc = ty * 4 + i;
        float s = g_invxn[n * LL + l0 + lloc];
        float v = ss[tx][lloc] * s;
        __half h  = __float2half(v);
        float  hf = __half2float(h);
        __half l  = __float2half((v - hf) * 64.0f);
        __half hs = __float2half(hf * 0.015625f);
        __half* dst = g_A + ((size_t)(n * LL + l0 + lloc)) * K3 + c0 + tx;
        dst[0]   = h;
        dst[256] = l;
        dst[512] = hs;
    }
}

// ---------------------------------------------------------------------------
// Kernel 4: HMMA GEMM via mma.sync + ldmatrix, 3-stage cp.async pipeline.
// CTA tile 128(l) x 128(p), 8 warps in 2x4 (warp tile 64x32), BK=64,
// stride 144 B (conflict-free), 2 CTAs/SM.
// One barrier per chunk: wait -> BAR -> issue loads kc+2 -> compute kc.
// The stage written by kc+2's loads was last read at kc-1, which the BAR
// orders; the BAR also publishes chunk kc's data to all warps.
// ---------------------------------------------------------------------------
#define GBK    64
#define NCHUNK (K3 / GBK)          // 12
#define ASTRB  144                 // smem row stride in bytes (72 halves)
#define STAGE_BYTES (128 * ASTRB)  // 18432 per operand
#define SM_A_OFF(s) ((s) * 2 * STAGE_BYTES)
#define SM_B_OFF(s) ((s) * 2 * STAGE_BYTES + STAGE_BYTES)
#define SMEM_GEMM  (6 * STAGE_BYTES)   // 110592 (3 stages)

__device__ __forceinline__ uint32_t smem_u32(const void* p) {
    uint32_t a;
    asm("{ .reg .u64 t; cvta.to.shared.u64 t, %1; cvt.u32.u64 %0, t; }" : "=r"(a) : "l"(p));
    return a;
}
#define CP16(sm_addr, gptr) \
    asm volatile("cp.async.cg.shared.global [%0], [%1], 16;" :: "r"(sm_addr), "l"(gptr) : "memory")
#define CP_COMMIT() asm volatile("cp.async.commit_group;" ::: "memory")
#define CP_WAIT(N)  asm volatile("cp.async.wait_group %0;" :: "n"(N) : "memory")

#define LDSM4(R0, R1, R2, R3, ADDR) \
    asm volatile("ldmatrix.sync.aligned.m8n8.x4.shared.b16 {%0,%1,%2,%3}, [%4];" \
        : "=r"(R0), "=r"(R1), "=r"(R2), "=r"(R3) : "r"(ADDR))

__device__ __forceinline__ void mma_fp16(float* c, const uint32_t* a,
                                         uint32_t b0, uint32_t b1) {
    asm volatile(
        "mma.sync.aligned.m16n8k16.row.col.f32.f16.f16.f32 "
        "{%0,%1,%2,%3}, {%4,%5,%6,%7}, {%8,%9}, {%0,%1,%2,%3};"
        : "+f"(c[0]), "+f"(c[1]), "+f"(c[2]), "+f"(c[3])
        : "r"(a[0]), "r"(a[1]), "r"(a[2]), "r"(a[3]), "r"(b0), "r"(b1));
}

__global__ __launch_bounds__(256, 2) void gemm_mma() {
    extern __shared__ __align__(1024) char sm[];
    uint32_t smb = smem_u32(sm);

    int tid  = threadIdx.x;
    int lane = tid & 31;
    int warp = tid >> 5;
    int wm   = warp & 1;        // 0..1  (M half, 64 rows)
    int wn   = warp >> 1;       // 0..3  (N quarter, 32 cols)

    int n    = blockIdx.z;
    int pBlk = blockIdx.x * 128;
    int lBlk = blockIdx.y * 128;

    const __half* Ag = g_A + ((size_t)(n * LL + lBlk)) * K3;
    const __half* Bg = g_B + (size_t)pBlk * K3;

    #define LOADCHUNK(KC, S)                                                     \
    {                                                                            \
        int kc_ = (KC);                                                          \
        uint32_t sa = smb + SM_A_OFF(S);                                         \
        uint32_t sb = smb + SM_B_OFF(S);                                         \
        _Pragma("unroll")                                                        \
        for (int j = 0; j < 4; j++) {                                            \
            int u = tid + j * 256;                                               \
            int row = u >> 3, seg = u & 7;                                       \
            CP16(sa + row * ASTRB + seg * 16,                                    \
                 Ag + (size_t)row * K3 + kc_ * GBK + seg * 8);                   \
        }                                                                        \
        _Pragma("unroll")                                                        \
        for (int j = 0; j < 4; j++) {                                            \
            int u = tid + j * 256;                                               \
            int row = u >> 3, seg = u & 7;                                       \
            CP16(sb + row * ASTRB + seg * 16,                                    \
                 Bg + (size_t)row * K3 + kc_ * GBK + seg * 8);                   \
        }                                                                        \
    }

    float acc[4][4][4];
    #pragma unroll
    for (int i = 0; i < 4; i++)
        #pragma unroll
        for (int j = 0; j < 4; j++)
            #pragma unroll
            for (int q = 0; q < 4; q++) acc[i][j][q] = 0.f;

    // ldmatrix lane-address decomposition (validated in R12).
    int lrow = lane & 7;
    int lm   = lane >> 3;   // 0..3
    uint32_t aOff = (uint32_t)((wm * 64 + (lm & 1) * 8 + lrow) * ASTRB + (lm >> 1) * 16);
    uint32_t bOff = (uint32_t)((wn * 32 + (lm >> 1) * 8 + lrow) * ASTRB + (lm & 1) * 16);

    LOADCHUNK(0, 0);
    CP_COMMIT();
    LOADCHUNK(1, 1);
    CP_COMMIT();

    int s = 0;
    #pragma unroll 1
    for (int kc = 0; kc < NCHUNK; kc++) {
        if (kc < NCHUNK - 1) { CP_WAIT(1); } else { CP_WAIT(0); }
        __syncthreads();
        if (kc + 2 < NCHUNK) {
            int s2 = s + 2; if (s2 >= 3) s2 -= 3;
            LOADCHUNK(kc + 2, s2);
            CP_COMMIT();
        }

        uint32_t sA = smb + SM_A_OFF(s) + aOff;
        uint32_t sB = smb + SM_B_OFF(s) + bOff;

        #pragma unroll
        for (int ks = 0; ks < GBK / 16; ks++) {
            uint32_t a[4][4], b[2][4];
            #pragma unroll
            for (int mt = 0; mt < 4; mt++)
                LDSM4(a[mt][0], a[mt][1], a[mt][2], a[mt][3],
                      sA + mt * (16 * ASTRB) + ks * 32);
            #pragma unroll
            for (int nt2 = 0; nt2 < 2; nt2++)
                LDSM4(b[nt2][0], b[nt2][1], b[nt2][2], b[nt2][3],
                      sB + nt2 * (16 * ASTRB) + ks * 32);
            #pragma unroll
            for (int mt = 0; mt < 4; mt++)
                #pragma unroll
                for (int nt = 0; nt < 4; nt++)
                    mma_fp16(acc[mt][nt], a[mt],
                             b[nt >> 1][(nt & 1) * 2], b[nt >> 1][(nt & 1) * 2 + 1]);
        }
        if (++s == 3) s = 0;
    }

    // Epilogue: write g_cos[n][l][p]
    int r  = lane >> 2;        // 0..7
    int cq = lane & 3;         // 0..3
    #pragma unroll
    for (int mt = 0; mt < 4; mt++) {
        int l0 = lBlk + wm * 64 + mt * 16 + r;
        float* row0 = g_cos + ((size_t)(n * LL + l0)) * PP + pBlk;
        float* row1 = g_cos + ((size_t)(n * LL + l0 + 8)) * PP + pBlk;
        #pragma unroll
        for (int nt = 0; nt < 4; nt++) {
            int p = wn * 32 + nt * 8 + cq * 2;
            float2 v0 = make_float2(acc[mt][nt][0], acc[mt][nt][1]);
            float2 v1 = make_float2(acc[mt][nt][2], acc[mt][nt][3]);
            *(float2*)&row0[p] = v0;
            *(float2*)&row1[p] = v1;
        }
    }
}

// ---------------------------------------------------------------------------
// Kernel 5: per-pixel exact top-102.
//   Phase A: OCTAL search — 7 probe thresholds per round, bracket narrows 8x
//            per round in value space (~4 rounds vs ~12 binary rounds; one
//            barrier per round is the win).
//   Phase B: collect candidates, exact rank via broadcast-LDS sweep,
//            warp-0 shfl-tree sum (fixed order, deterministic).
// Gather: float4 pool loads, KEEP terms split across 4 thread-groups.
// ---------------------------------------------------------------------------
#define CAND_MAX 150
#define CAND_ARR 320
#define NRND     10

__global__ __launch_bounds__(256) void topk_recon(const float* __restrict__ pool,
                                                  float* __restrict__ out) {
    int blk = blockIdx.x;            // n*1024 + l
    int n = blk >> 10, l = blk & (LL - 1);
    const float* row = g_cos + (size_t)blk * PP;

    __shared__ float  sv[PP];
    __shared__ int    cnt[NRND][8];
    __shared__ int    s_cnt;
    __shared__ float  s_ckey[CAND_ARR];
    __shared__ int    s_cidx[CAND_ARR];
    __shared__ int    s_idx[KEEP];
    __shared__ float  s_val[KEEP];
    __shared__ float  s_invS;
    __shared__ float4 s_part[4][64];

    int tid = threadIdx.x;

    float4 r0 = *(const float4*)&row[tid * 4];
    float4 r1 = *(const float4*)&row[1024 + tid * 4];
    *(float4*)&sv[tid * 4]        = r0;
    *(float4*)&sv[1024 + tid * 4] = r1;

    float a[8];
    a[0] = fabsf(r0.x); a[1] = fabsf(r0.y); a[2] = fabsf(r0.z); a[3] = fabsf(r0.w);
    a[4] = fabsf(r1.x); a[5] = fabsf(r1.y); a[6] = fabsf(r1.z); a[7] = fabsf(r1.w);

    if (tid < NRND * 8) ((int*)cnt)[tid] = 0;
    if (tid == 0) s_cnt = 0;
    __syncthreads();

    // Phase A: octal search. Invariant: count(key >= lo) >= KEEP.
    unsigned lo = 0u, hi = 0x3FC00000u;
    int cntLo = PP;
    #pragma unroll 1
    for (int rnd = 0; rnd < NRND && cntLo > CAND_MAX; rnd++) {
        unsigned step = (hi - lo) >> 3;
        if (step == 0) break;
        float t[7];
        #pragma unroll
        for (int i = 0; i < 7; i++) t[i] = __uint_as_float(lo + step * (i + 1));
        int c[7] = {0, 0, 0, 0, 0, 0, 0};
        #pragma unroll
        for (int j = 0; j < 8; j++) {
            float k = a[j];
            #pragma unroll
            for (int i = 0; i < 7; i++) c[i] += (k >= t[i]);
        }
        #pragma unroll
        for (int i = 0; i < 7; i++) {
            int sum = __reduce_add_sync(0xFFFFFFFFu, c[i]);
            if ((tid & 31) == 0) atomicAdd(&cnt[rnd][i], sum);
        }
        __syncthreads();
        // All threads derive the same new bracket from shared counts.
        int newI = 0;
        #pragma unroll
        for (int i = 1; i <= 7; i++)
            if (cnt[rnd][i - 1] >= KEEP) newI = i;
        unsigned oldLo = lo;
        if (newI > 0) { lo = oldLo + step * newI; cntLo = cnt[rnd][newI - 1]; }
        if (newI < 7) hi = oldLo + step * (newI + 1);
    }
    float loF = __uint_as_float(lo);

    // Phase B1: collect candidates (key >= loF).
    #pragma unroll
    for (int j = 0; j < 8; j++) {
        if (a[j] >= loF) {
            int idx = (j < 4) ? (tid * 4 + j) : (1024 + tid * 4 + (j - 4));
            int slot = atomicAdd(&s_cnt, 1);
            if (slot < CAND_ARR) {
                s_ckey[slot] = a[j];
                s_cidx[slot] = idx;
            }
        }
    }
    __syncthreads();

    int C = s_cnt;
    if (C > CAND_ARR) C = CAND_ARR;   // safety (unreachable with real data)

    // Phase B2: exact rank per candidate (broadcast LDS sweep).
    for (int i = tid; i < C; i += 256) {
        float ki = s_ckey[i];
        int   ii = s_cidx[i];
        int rank = 0;
        #pragma unroll 4
        for (int j = 0; j < C; j++) {
            float kj = s_ckey[j];
            int   ij = s_cidx[j];
            rank += (kj > ki) | ((kj == ki) & (ij < ii));
        }
        if (rank < KEEP) {
            s_idx[rank] = ii;
            s_val[rank] = sv[ii];
        }
    }
    __syncthreads();

    // Deterministic parallel sum (warp 0, fixed-order shfl tree).
    if (tid < 32) {
        float v = s_val[tid] + s_val[tid + 32] + s_val[tid + 64]
                + ((tid + 96 < KEEP) ? s_val[tid + 96] : 0.f);
        #pragma unroll
        for (int off = 16; off > 0; off >>= 1)
            v += __shfl_down_sync(0xFFFFFFFFu, v, off);
        if (tid == 0) s_invS = 1.0f / v;
    }
    __syncthreads();

    // Sparse reconstruction, float4 + j-split across 4 thread-groups.
    {
        const float4* pool4 = (const float4*)pool;
        int g = tid >> 6;
        int t = tid & 63;
        float4 acc = make_float4(0.f, 0.f, 0.f, 0.f);
        #pragma unroll 4
        for (int j = g; j < KEEP; j += 4) {
            float  w  = s_val[j];
            float4 pv = __ldg(&pool4[(size_t)s_idx[j] * 64 + t]);
            acc.x = fmaf(w, pv.x, acc.x);
            acc.y = fmaf(w, pv.y, acc.y);
            acc.z = fmaf(w, pv.z, acc.z);
            acc.w = fmaf(w, pv.w, acc.w);
        }
        s_part[g][t] = acc;
    }
    __syncthreads();

    {
        int t    = tid >> 2;        // 0..63
        int comp = tid & 3;         // 0..3  -> channel c = 4t+comp = tid
        float v = ((const float*)&s_part[0][t])[comp]
                + ((const float*)&s_part[1][t])[comp]
                + ((const float*)&s_part[2][t])[comp]
                + ((const float*)&s_part[3][t])[comp];
        out[(size_t)n * CCH * LL + (size_t)tid * LL + l] = v * s_invS;
    }
}

// ---------------------------------------------------------------------------
// Launch
// ---------------------------------------------------------------------------
extern "C" void kernel_launch(void* const* d_in, const int* in_sizes, int n_in,
                              void* d_out, int out_size) {
    const float* x    = (const float*)d_in[0];  // [16, 256, 32, 32]
    const float* pool = (const float*)d_in[1];  // [2048, 256]
    float* out        = (float*)d_out;          // [16, 256, 32, 32]

    cudaFuncSetAttribute(gemm_mma, cudaFuncAttributeMaxDynamicSharedMemorySize, SMEM_GEMM);

    prep_pool<<<PP, 256>>>(pool);
    prep_xnorm<<<(NB * LL) / 256, 256>>>(x);
    prep_xT<<<dim3(LL / 32, CCH / 32, NB), 256>>>(x);
    gemm_mma<<<dim3(PP / 128, LL / 128, NB), 256, SMEM_GEMM>>>();
    topk_recon<<<NB * LL, 256>>>(pool, out);
}

// round 14
// speedup vs baseline: 1.1253x; 1.1253x over previous
#include <cuda_runtime.h>
#include <cuda_fp16.h>
#include <math.h>
#include <stdint.h>

// Shapes (fixed by the problem)
#define NB   16
#define CCH  256
#define HH   32
#define WW   32
#define LL   (HH*WW)       // 1024
#define PP   2048
#define KEEP 102           // int(0.05 * 2048)
#define K3   768           // 3x fp16 split K (h | l*64 | h/64) . (h | h/64 | l*64)

// ---------------------------------------------------------------------------
// Scratch (device globals only; no allocations allowed)
// ---------------------------------------------------------------------------
__device__ float  g_invxn[NB * LL];                    // 64 KB
__device__ __half g_A[(size_t)NB * LL * K3];           // 25 MB  A' split of x^T * invxn
__device__ __half g_B[(size_t)PP * K3];                // 3 MB   B' split of poolN
__device__ __half g_pool16[PP * CCH];                  // 1 MB   fp16 copy of raw pool (gather)
__device__ float  g_cos[(size_t)NB * LL * PP];         // 134 MB

// ---------------------------------------------------------------------------
// Kernel 1: normalize pool rows -> fp16 split B'; also write fp16 pool copy.
// ---------------------------------------------------------------------------
__global__ void prep_pool(const float* __restrict__ pool) {
    int p = blockIdx.x;
    int c = threadIdx.x;
    float v = pool[p * CCH + c];
    g_pool16[p * CCH + c] = __float2half(v);
    __shared__ float red[256];
    red[c] = v * v;
    __syncthreads();
    #pragma unroll
    for (int s = 128; s > 0; s >>= 1) {
        if (c < s) red[c] += red[c + s];
        __syncthreads();
    }
    float vn = v * (1.0f / sqrtf(red[0]));
    __half h  = __float2half(vn);
    float  hf = __half2float(h);
    __half l  = __float2half((vn - hf) * 64.0f);     // scaled residual (normal range)
    __half hs = __float2half(hf * 0.015625f);        // h / 64 (exact pow2 scale)
    __half* dst = g_B + (size_t)p * K3 + c;
    dst[0]   = h;
    dst[256] = hs;
    dst[512] = l;
}

// ---------------------------------------------------------------------------
// Kernel 2: per-pixel inverse norm of x.
// ---------------------------------------------------------------------------
__global__ void prep_xnorm(const float* __restrict__ x) {
    int idx = blockIdx.x * 256 + threadIdx.x;   // 0 .. 16383
    int n = idx >> 10, l = idx & (LL - 1);
    const float* xp = x + (size_t)n * CCH * LL + l;
    float s = 0.f;
    #pragma unroll 8
    for (int c = 0; c < CCH; c++) {
        float v = xp[c * LL];
        s = fmaf(v, v, s);
    }
    g_invxn[idx] = 1.0f / sqrtf(s);
}

// ---------------------------------------------------------------------------
// Kernel 3: transpose x [n][c][l] -> A' [n][l][K3] fp16 split [h | l*64 | h/64],
// with invxn folded in. 32x32 tiles, 256 threads.
// ---------------------------------------------------------------------------
__global__ __launch_bounds__(256) void prep_xT(const float* __restrict__ x) {
    int n  = blockIdx.z;
    int c0 = blockIdx.y * 32;
    int l0 = blockIdx.x * 32;
    int tx = threadIdx.x & 31;
    int ty = threadIdx.x >> 5;     // 0..7
    __shared__ float ss[32][33];

    const float* xp = x + (size_t)n * CCH * LL;
    #pragma unroll
    for (int i = 0; i < 4; i++) {
        int c = ty * 4 + i;
        ss[c][tx] = xp[(size_t)(c0 + c) * LL + l0 + tx];
    }
    __syncthreads();
    #pragma unroll
    for (int i = 0; i < 4; i++) {
        int lloc = ty * 4 + i;
        float s = g_invxn[n * LL + l0 + lloc];
        float v = ss[tx][lloc] * s;
        __half h  = __float2half(v);
        float  hf = __half2float(h);
        __half l  = __float2half((v - hf) * 64.0f);
        __half hs = __float2half(hf * 0.015625f);
        __half* dst = g_A + ((size_t)(n * LL + l0 + lloc)) * K3 + c0 + tx;
        dst[0]   = h;
        dst[256] = l;
        dst[512] = hs;
    }
}

// ---------------------------------------------------------------------------
// Kernel 4: HMMA GEMM via mma.sync + ldmatrix, 3-stage cp.async pipeline.
// (R13: 150.9us, tensor=56%. Unchanged.)
// ---------------------------------------------------------------------------
#define GBK    64
#define NCHUNK (K3 / GBK)          // 12
#define ASTRB  144                 // smem row stride in bytes (72 halves)
#define STAGE_BYTES (128 * ASTRB)  // 18432 per operand
#define SM_A_OFF(s) ((s) * 2 * STAGE_BYTES)
#define SM_B_OFF(s) ((s) * 2 * STAGE_BYTES + STAGE_BYTES)
#define SMEM_GEMM  (6 * STAGE_BYTES)   // 110592 (3 stages)

__device__ __forceinline__ uint32_t smem_u32(const void* p) {
    uint32_t a;
    asm("{ .reg .u64 t; cvta.to.shared.u64 t, %1; cvt.u32.u64 %0, t; }" : "=r"(a) : "l"(p));
    return a;
}
#define CP16(sm_addr, gptr) \
    asm volatile("cp.async.cg.shared.global [%0], [%1], 16;" :: "r"(sm_addr), "l"(gptr) : "memory")
#define CP_COMMIT() asm volatile("cp.async.commit_group;" ::: "memory")
#define CP_WAIT(N)  asm volatile("cp.async.wait_group %0;" :: "n"(N) : "memory")

#define LDSM4(R0, R1, R2, R3, ADDR) \
    asm volatile("ldmatrix.sync.aligned.m8n8.x4.shared.b16 {%0,%1,%2,%3}, [%4];" \
        : "=r"(R0), "=r"(R1), "=r"(R2), "=r"(R3) : "r"(ADDR))

__device__ __forceinline__ void mma_fp16(float* c, const uint32_t* a,
                                         uint32_t b0, uint32_t b1) {
    asm volatile(
        "mma.sync.aligned.m16n8k16.row.col.f32.f16.f16.f32 "
        "{%0,%1,%2,%3}, {%4,%5,%6,%7}, {%8,%9}, {%0,%1,%2,%3};"
        : "+f"(c[0]), "+f"(c[1]), "+f"(c[2]), "+f"(c[3])
        : "r"(a[0]), "r"(a[1]), "r"(a[2]), "r"(a[3]), "r"(b0), "r"(b1));
}

__global__ __launch_bounds__(256, 2) void gemm_mma() {
    extern __shared__ __align__(1024) char sm[];
    uint32_t smb = smem_u32(sm);

    int tid  = threadIdx.x;
    int lane = tid & 31;
    int warp = tid >> 5;
    int wm   = warp & 1;        // 0..1  (M half, 64 rows)
    int wn   = warp >> 1;       // 0..3  (N quarter, 32 cols)

    int n    = blockIdx.z;
    int pBlk = blockIdx.x * 128;
    int lBlk = blockIdx.y * 128;

    const __half* Ag = g_A + ((size_t)(n * LL + lBlk)) * K3;
    const __half* Bg = g_B + (size_t)pBlk * K3;

    #define LOADCHUNK(KC, S)                                                     \
    {                                                                            \
        int kc_ = (KC);                                                          \
        uint32_t sa = smb + SM_A_OFF(S);                                         \
        uint32_t sb = smb + SM_B_OFF(S);                                         \
        _Pragma("unroll")                                                        \
        for (int j = 0; j < 4; j++) {                                            \
            int u = tid + j * 256;                                               \
            int row = u >> 3, seg = u & 7;                                       \
            CP16(sa + row * ASTRB + seg * 16,                                    \
                 Ag + (size_t)row * K3 + kc_ * GBK + seg * 8);                   \
        }                                                                        \
        _Pragma("unroll")                                                        \
        for (int j = 0; j < 4; j++) {                                            \
            int u = tid + j * 256;                                               \
            int row = u >> 3, seg = u & 7;                                       \
            CP16(sb + row * ASTRB + seg * 16,                                    \
                 Bg + (size_t)row * K3 + kc_ * GBK + seg * 8);                   \
        }                                                                        \
    }

    float acc[4][4][4];
    #pragma unroll
    for (int i = 0; i < 4; i++)
        #pragma unroll
        for (int j = 0; j < 4; j++)
            #pragma unroll
            for (int q = 0; q < 4; q++) acc[i][j][q] = 0.f;

    // ldmatrix lane-address decomposition (validated in R12).
    int lrow = lane & 7;
    int lm   = lane >> 3;   // 0..3
    uint32_t aOff = (uint32_t)((wm * 64 + (lm & 1) * 8 + lrow) * ASTRB + (lm >> 1) * 16);
    uint32_t bOff = (uint32_t)((wn * 32 + (lm >> 1) * 8 + lrow) * ASTRB + (lm & 1) * 16);

    LOADCHUNK(0, 0);
    CP_COMMIT();
    LOADCHUNK(1, 1);
    CP_COMMIT();

    int s = 0;
    #pragma unroll 1
    for (int kc = 0; kc < NCHUNK; kc++) {
        if (kc < NCHUNK - 1) { CP_WAIT(1); } else { CP_WAIT(0); }
        __syncthreads();
        if (kc + 2 < NCHUNK) {
            int s2 = s + 2; if (s2 >= 3) s2 -= 3;
            LOADCHUNK(kc + 2, s2);
            CP_COMMIT();
        }

        uint32_t sA = smb + SM_A_OFF(s) + aOff;
        uint32_t sB = smb + SM_B_OFF(s) + bOff;

        #pragma unroll
        for (int ks = 0; ks < GBK / 16; ks++) {
            uint32_t a[4][4], b[2][4];
            #pragma unroll
            for (int mt = 0; mt < 4; mt++)
                LDSM4(a[mt][0], a[mt][1], a[mt][2], a[mt][3],
                      sA + mt * (16 * ASTRB) + ks * 32);
            #pragma unroll
            for (int nt2 = 0; nt2 < 2; nt2++)
                LDSM4(b[nt2][0], b[nt2][1], b[nt2][2], b[nt2][3],
                      sB + nt2 * (16 * ASTRB) + ks * 32);
            #pragma unroll
            for (int mt = 0; mt < 4; mt++)
                #pragma unroll
                for (int nt = 0; nt < 4; nt++)
                    mma_fp16(acc[mt][nt], a[mt],
                             b[nt >> 1][(nt & 1) * 2], b[nt >> 1][(nt & 1) * 2 + 1]);
        }
        if (++s == 3) s = 0;
    }

    // Epilogue: write g_cos[n][l][p]
    int r  = lane >> 2;        // 0..7
    int cq = lane & 3;         // 0..3
    #pragma unroll
    for (int mt = 0; mt < 4; mt++) {
        int l0 = lBlk + wm * 64 + mt * 16 + r;
        float* row0 = g_cos + ((size_t)(n * LL + l0)) * PP + pBlk;
        float* row1 = g_cos + ((size_t)(n * LL + l0 + 8)) * PP + pBlk;
        #pragma unroll
        for (int nt = 0; nt < 4; nt++) {
            int p = wn * 32 + nt * 8 + cq * 2;
            float2 v0 = make_float2(acc[mt][nt][0], acc[mt][nt][1]);
            float2 v1 = make_float2(acc[mt][nt][2], acc[mt][nt][3]);
            *(float2*)&row0[p] = v0;
            *(float2*)&row1[p] = v1;
        }
    }
}

// ---------------------------------------------------------------------------
// Kernel 5: per-pixel exact top-102.
//   Phase A: BINARY search (R12-proven; R13 octal regressed — REDUX ops,
//            not barriers, are the unit of cost here).
//   Phase B: collect candidates, exact rank via broadcast-LDS sweep,
//            warp-0 fixed-order shfl sum (deterministic).
// Gather: fp16 pool copy (halves L2 traffic vs fp32; selection & weights
// stay fp32), KEEP terms split across 4 thread-groups, combined via smem.
// ---------------------------------------------------------------------------
#define CAND_MAX 150
#define CAND_ARR 320
#define MAXIT    32

__global__ __launch_bounds__(256) void topk_recon(const float* __restrict__ pool,
                                                  float* __restrict__ out) {
    int blk = blockIdx.x;            // n*1024 + l
    int n = blk >> 10, l = blk & (LL - 1);
    const float* row = g_cos + (size_t)blk * PP;

    __shared__ float  sv[PP];
    __shared__ int    cnt[MAXIT];
    __shared__ int    s_cnt;
    __shared__ float  s_ckey[CAND_ARR];
    __shared__ int    s_cidx[CAND_ARR];
    __shared__ int    s_idx[KEEP];
    __shared__ float  s_val[KEEP];
    __shared__ float  s_invS;
    __shared__ float4 s_part[4][64];

    int tid = threadIdx.x;

    float4 r0 = *(const float4*)&row[tid * 4];
    float4 r1 = *(const float4*)&row[1024 + tid * 4];
    *(float4*)&sv[tid * 4]        = r0;
    *(float4*)&sv[1024 + tid * 4] = r1;

    float a0 = fabsf(r0.x), a1 = fabsf(r0.y), a2 = fabsf(r0.z), a3 = fabsf(r0.w);
    float a4 = fabsf(r1.x), a5 = fabsf(r1.y), a6 = fabsf(r1.z), a7 = fabsf(r1.w);

    if (tid < MAXIT) cnt[tid] = 0;
    if (tid == 0) s_cnt = 0;
    __syncthreads();

    // Phase A: binary search. Invariant: count(key >= lo) >= KEEP.
    unsigned lo = 0u, hi = 0x3FC00000u;
    int cntLo = PP;
    int it = 0;
    while (cntLo > CAND_MAX && it < MAXIT) {
        unsigned mid = (lo + hi) >> 1;
        float mf = __uint_as_float(mid);
        int c = (a0 >= mf) + (a1 >= mf) + (a2 >= mf) + (a3 >= mf)
              + (a4 >= mf) + (a5 >= mf) + (a6 >= mf) + (a7 >= mf);
        c = __reduce_add_sync(0xFFFFFFFFu, c);
        if ((tid & 31) == 0) atomicAdd(&cnt[it], c);
        __syncthreads();
        int cm = cnt[it];
        if (cm >= KEEP) { lo = mid; cntLo = cm; }
        else            { hi = mid; }
        it++;
    }
    float loF = __uint_as_float(lo);

    // Phase B1: collect candidates (key >= loF).
    #define CAND(AV, IDX)                                               \
        {                                                               \
            float av_ = (AV);                                           \
            if (av_ >= loF) {                                           \
                int slot = atomicAdd(&s_cnt, 1);                        \
                if (slot < CAND_ARR) {                                  \
                    s_ckey[slot] = av_; s_cidx[slot] = (IDX);           \
                }                                                       \
            }                                                           \
        }
    int base = tid * 4;
    CAND(a0, base + 0)
    CAND(a1, base + 1)
    CAND(a2, base + 2)
    CAND(a3, base + 3)
    CAND(a4, 1024 + base + 0)
    CAND(a5, 1024 + base + 1)
    CAND(a6, 1024 + base + 2)
    CAND(a7, 1024 + base + 3)
    #undef CAND
    __syncthreads();

    int C = s_cnt;
    if (C > CAND_ARR) C = CAND_ARR;   // safety (unreachable with real data)

    // Phase B2: exact rank per candidate (broadcast LDS sweep).
    for (int i = tid; i < C; i += 256) {
        float ki = s_ckey[i];
        int   ii = s_cidx[i];
        int rank = 0;
        #pragma unroll 4
        for (int j = 0; j < C; j++) {
            float kj = s_ckey[j];
            int   ij = s_cidx[j];
            rank += (kj > ki) | ((kj == ki) & (ij < ii));
        }
        if (rank < KEEP) {
            s_idx[rank] = ii;
            s_val[rank] = sv[ii];
        }
    }
    __syncthreads();

    // Deterministic parallel sum (warp 0, fixed-order shfl tree).
    if (tid < 32) {
        float v = s_val[tid] + s_val[tid + 32] + s_val[tid + 64]
                + ((tid + 96 < KEEP) ? s_val[tid + 96] : 0.f);
        #pragma unroll
        for (int off = 16; off > 0; off >>= 1)
            v += __shfl_down_sync(0xFFFFFFFFu, v, off);
        if (tid == 0) s_invS = 1.0f / v;
    }
    __syncthreads();

    // Sparse reconstruction from fp16 pool copy (half the L2 bytes).
    // Group g = tid>>6 handles keeps j == g (mod 4); thread covers channels
    // [4t, 4t+4), loading 4 halves (8 B) per term. Weights stay fp32.
    {
        int g = tid >> 6;
        int t = tid & 63;
        float4 acc = make_float4(0.f, 0.f, 0.f, 0.f);
        #pragma unroll 4
        for (int j = g; j < KEEP; j += 4) {
            float w = s_val[j];
            const __half2* hp = (const __half2*)(g_pool16 + (size_t)s_idx[j] * CCH + t * 4);
            __half2 h01 = __ldg(&hp[0]);
            __half2 h23 = __ldg(&hp[1]);
            float2 f01 = __half22float2(h01);
            float2 f23 = __half22float2(h23);
            acc.x = fmaf(w, f01.x, acc.x);
            acc.y = fmaf(w, f01.y, acc.y);
            acc.z = fmaf(w, f23.x, acc.z);
            acc.w = fmaf(w, f23.y, acc.w);
        }
        s_part[g][t] = acc;
    }
    __syncthreads();

    {
        int t    = tid >> 2;        // 0..63
        int comp = tid & 3;         // 0..3  -> channel c = 4t+comp = tid
        float v = ((const float*)&s_part[0][t])[comp]
                + ((const float*)&s_part[1][t])[comp]
                + ((const float*)&s_part[2][t])[comp]
                + ((const float*)&s_part[3][t])[comp];
        out[(size_t)n * CCH * LL + (size_t)tid * LL + l] = v * s_invS;
    }
}

// ---------------------------------------------------------------------------
// Launch
// ---------------------------------------------------------------------------
extern "C" void kernel_launch(void* const* d_in, const int* in_sizes, int n_in,
                              void* d_out, int out_size) {
    const float* x    = (const float*)d_in[0];  // [16, 256, 32, 32]
    const float* pool = (const float*)d_in[1];  // [2048, 256]
    float* out        = (float*)d_out;          // [16, 256, 32, 32]

    cudaFuncSetAttribute(gemm_mma, cudaFuncAttributeMaxDynamicSharedMemorySize, SMEM_GEMM);

    prep_pool<<<PP, 256>>>(pool);
    prep_xnorm<<<(NB * LL) / 256, 256>>>(x);
    prep_xT<<<dim3(LL / 32, CCH / 32, NB), 256>>>(x);
    gemm_mma<<<dim3(PP / 128, LL / 128, NB), 256, SMEM_GEMM>>>();
    topk_recon<<<NB * LL, 256>>>(pool, out);
}

// round 15
// speedup vs baseline: 1.1890x; 1.0566x over previous
#include <cuda_runtime.h>
#include <cuda_fp16.h>
#include <math.h>
#include <stdint.h>

// Shapes (fixed by the problem)
#define NB   16
#define CCH  256
#define HH   32
#define WW   32
#define LL   (HH*WW)       // 1024
#define PP   2048
#define KEEP 102           // int(0.05 * 2048)
#define K3   768           // 3x fp16 split K (h | l*64 | h/64) . (h | h/64 | l*64)

// ---------------------------------------------------------------------------
// Scratch (device globals only; no allocations allowed)
// ---------------------------------------------------------------------------
__device__ float  g_invxn[NB * LL];                    // 64 KB
__device__ __half g_A[(size_t)NB * LL * K3];           // 25 MB  A' split of x^T * invxn
__device__ __half g_B[(size_t)PP * K3];                // 3 MB   B' split of poolN
__device__ __half g_pool16[PP * CCH];                  // 1 MB   fp16 copy of raw pool (gather)
__device__ float  g_cos[(size_t)NB * LL * PP];         // 134 MB

// ---------------------------------------------------------------------------
// Kernel 1: normalize pool rows -> fp16 split B'; also write fp16 pool copy.
// ---------------------------------------------------------------------------
__global__ void prep_pool(const float* __restrict__ pool) {
    int p = blockIdx.x;
    int c = threadIdx.x;
    float v = pool[p * CCH + c];
    g_pool16[p * CCH + c] = __float2half(v);
    __shared__ float red[256];
    red[c] = v * v;
    __syncthreads();
    #pragma unroll
    for (int s = 128; s > 0; s >>= 1) {
        if (c < s) red[c] += red[c + s];
        __syncthreads();
    }
    float vn = v * (1.0f / sqrtf(red[0]));
    __half h  = __float2half(vn);
    float  hf = __half2float(h);
    __half l  = __float2half((vn - hf) * 64.0f);     // scaled residual (normal range)
    __half hs = __float2half(hf * 0.015625f);        // h / 64 (exact pow2 scale)
    __half* dst = g_B + (size_t)p * K3 + c;
    dst[0]   = h;
    dst[256] = hs;
    dst[512] = l;
}

// ---------------------------------------------------------------------------
// Kernel 2: per-pixel inverse norm of x.
// ---------------------------------------------------------------------------
__global__ void prep_xnorm(const float* __restrict__ x) {
    int idx = blockIdx.x * 256 + threadIdx.x;   // 0 .. 16383
    int n = idx >> 10, l = idx & (LL - 1);
    const float* xp = x + (size_t)n * CCH * LL + l;
    float s = 0.f;
    #pragma unroll 8
    for (int c = 0; c < CCH; c++) {
        float v = xp[c * LL];
        s = fmaf(v, v, s);
    }
    g_invxn[idx] = 1.0f / sqrtf(s);
}

// ---------------------------------------------------------------------------
// Kernel 3: transpose x [n][c][l] -> A' [n][l][K3] fp16 split [h | l*64 | h/64],
// with invxn folded in. 32x32 tiles, 256 threads.
// ---------------------------------------------------------------------------
__global__ __launch_bounds__(256) void prep_xT(const float* __restrict__ x) {
    int n  = blockIdx.z;
    int c0 = blockIdx.y * 32;
    int l0 = blockIdx.x * 32;
    int tx = threadIdx.x & 31;
    int ty = threadIdx.x >> 5;     // 0..7
    __shared__ float ss[32][33];

    const float* xp = x + (size_t)n * CCH * LL;
    #pragma unroll
    for (int i = 0; i < 4; i++) {
        int c = ty * 4 + i;
        ss[c][tx] = xp[(size_t)(c0 + c) * LL + l0 + tx];
    }
    __syncthreads();
    #pragma unroll
    for (int i = 0; i < 4; i++) {
        int lloc = ty * 4 + i;
        float s = g_invxn[n * LL + l0 + lloc];
        float v = ss[tx][lloc] * s;
        __half h  = __float2half(v);
        float  hf = __half2float(h);
        __half l  = __float2half((v - hf) * 64.0f);
        __half hs = __float2half(hf * 0.015625f);
        __half* dst = g_A + ((size_t)(n * LL + l0 + lloc)) * K3 + c0 + tx;
        dst[0]   = h;
        dst[256] = l;
        dst[512] = hs;
    }
}

// ---------------------------------------------------------------------------
// Kernel 4: HMMA GEMM via mma.sync + ldmatrix, 3-stage cp.async pipeline.
// (R14: 151.7us, tensor=56%. Unchanged.)
// ---------------------------------------------------------------------------
#define GBK    64
#define NCHUNK (K3 / GBK)          // 12
#define ASTRB  144                 // smem row stride in bytes (72 halves)
#define STAGE_BYTES (128 * ASTRB)  // 18432 per operand
#define SM_A_OFF(s) ((s) * 2 * STAGE_BYTES)
#define SM_B_OFF(s) ((s) * 2 * STAGE_BYTES + STAGE_BYTES)
#define SMEM_GEMM  (6 * STAGE_BYTES)   // 110592 (3 stages)

__device__ __forceinline__ uint32_t smem_u32(const void* p) {
    uint32_t a;
    asm("{ .reg .u64 t; cvta.to.shared.u64 t, %1; cvt.u32.u64 %0, t; }" : "=r"(a) : "l"(p));
    return a;
}
#define CP16(sm_addr, gptr) \
    asm volatile("cp.async.cg.shared.global [%0], [%1], 16;" :: "r"(sm_addr), "l"(gptr) : "memory")
#define CP_COMMIT() asm volatile("cp.async.commit_group;" ::: "memory")
#define CP_WAIT(N)  asm volatile("cp.async.wait_group %0;" :: "n"(N) : "memory")

#define LDSM4(R0, R1, R2, R3, ADDR) \
    asm volatile("ldmatrix.sync.aligned.m8n8.x4.shared.b16 {%0,%1,%2,%3}, [%4];" \
        : "=r"(R0), "=r"(R1), "=r"(R2), "=r"(R3) : "r"(ADDR))

__device__ __forceinline__ void mma_fp16(float* c, const uint32_t* a,
                                         uint32_t b0, uint32_t b1) {
    asm volatile(
        "mma.sync.aligned.m16n8k16.row.col.f32.f16.f16.f32 "
        "{%0,%1,%2,%3}, {%4,%5,%6,%7}, {%8,%9}, {%0,%1,%2,%3};"
        : "+f"(c[0]), "+f"(c[1]), "+f"(c[2]), "+f"(c[3])
        : "r"(a[0]), "r"(a[1]), "r"(a[2]), "r"(a[3]), "r"(b0), "r"(b1));
}

__global__ __launch_bounds__(256, 2) void gemm_mma() {
    extern __shared__ __align__(1024) char sm[];
    uint32_t smb = smem_u32(sm);

    int tid  = threadIdx.x;
    int lane = tid & 31;
    int warp = tid >> 5;
    int wm   = warp & 1;        // 0..1  (M half, 64 rows)
    int wn   = warp >> 1;       // 0..3  (N quarter, 32 cols)

    int n    = blockIdx.z;
    int pBlk = blockIdx.x * 128;
    int lBlk = blockIdx.y * 128;

    const __half* Ag = g_A + ((size_t)(n * LL + lBlk)) * K3;
    const __half* Bg = g_B + (size_t)pBlk * K3;

    #define LOADCHUNK(KC, S)                                                     \
    {                                                                            \
        int kc_ = (KC);                                                          \
        uint32_t sa = smb + SM_A_OFF(S);                                         \
        uint32_t sb = smb + SM_B_OFF(S);                                         \
        _Pragma("unroll")                                                        \
        for (int j = 0; j < 4; j++) {                                            \
            int u = tid + j * 256;                                               \
            int row = u >> 3, seg = u & 7;                                       \
            CP16(sa + row * ASTRB + seg * 16,                                    \
                 Ag + (size_t)row * K3 + kc_ * GBK + seg * 8);                   \
        }                                                                        \
        _Pragma("unroll")                                                        \
        for (int j = 0; j < 4; j++) {                                            \
            int u = tid + j * 256;                                               \
            int row = u >> 3, seg = u & 7;                                       \
            CP16(sb + row * ASTRB + seg * 16,                                    \
                 Bg + (size_t)row * K3 + kc_ * GBK + seg * 8);                   \
        }                                                                        \
    }

    float acc[4][4][4];
    #pragma unroll
    for (int i = 0; i < 4; i++)
        #pragma unroll
        for (int j = 0; j < 4; j++)
            #pragma unroll
            for (int q = 0; q < 4; q++) acc[i][j][q] = 0.f;

    // ldmatrix lane-address decomposition (validated in R12).
    int lrow = lane & 7;
    int lm   = lane >> 3;   // 0..3
    uint32_t aOff = (uint32_t)((wm * 64 + (lm & 1) * 8 + lrow) * ASTRB + (lm >> 1) * 16);
    uint32_t bOff = (uint32_t)((wn * 32 + (lm >> 1) * 8 + lrow) * ASTRB + (lm & 1) * 16);

    LOADCHUNK(0, 0);
    CP_COMMIT();
    LOADCHUNK(1, 1);
    CP_COMMIT();

    int s = 0;
    #pragma unroll 1
    for (int kc = 0; kc < NCHUNK; kc++) {
        if (kc < NCHUNK - 1) { CP_WAIT(1); } else { CP_WAIT(0); }
        __syncthreads();
        if (kc + 2 < NCHUNK) {
            int s2 = s + 2; if (s2 >= 3) s2 -= 3;
            LOADCHUNK(kc + 2, s2);
            CP_COMMIT();
        }

        uint32_t sA = smb + SM_A_OFF(s) + aOff;
        uint32_t sB = smb + SM_B_OFF(s) + bOff;

        #pragma unroll
        for (int ks = 0; ks < GBK / 16; ks++) {
            uint32_t a[4][4], b[2][4];
            #pragma unroll
            for (int mt = 0; mt < 4; mt++)
                LDSM4(a[mt][0], a[mt][1], a[mt][2], a[mt][3],
                      sA + mt * (16 * ASTRB) + ks * 32);
            #pragma unroll
            for (int nt2 = 0; nt2 < 2; nt2++)
                LDSM4(b[nt2][0], b[nt2][1], b[nt2][2], b[nt2][3],
                      sB + nt2 * (16 * ASTRB) + ks * 32);
            #pragma unroll
            for (int mt = 0; mt < 4; mt++)
                #pragma unroll
                for (int nt = 0; nt < 4; nt++)
                    mma_fp16(acc[mt][nt], a[mt],
                             b[nt >> 1][(nt & 1) * 2], b[nt >> 1][(nt & 1) * 2 + 1]);
        }
        if (++s == 3) s = 0;
    }

    // Epilogue: write g_cos[n][l][p]
    int r  = lane >> 2;        // 0..7
    int cq = lane & 3;         // 0..3
    #pragma unroll
    for (int mt = 0; mt < 4; mt++) {
        int l0 = lBlk + wm * 64 + mt * 16 + r;
        float* row0 = g_cos + ((size_t)(n * LL + l0)) * PP + pBlk;
        float* row1 = g_cos + ((size_t)(n * LL + l0 + 8)) * PP + pBlk;
        #pragma unroll
        for (int nt = 0; nt < 4; nt++) {
            int p = wn * 32 + nt * 8 + cq * 2;
            float2 v0 = make_float2(acc[mt][nt][0], acc[mt][nt][1]);
            float2 v1 = make_float2(acc[mt][nt][2], acc[mt][nt][3]);
            *(float2*)&row0[p] = v0;
            *(float2*)&row1[p] = v1;
        }
    }
}

// ---------------------------------------------------------------------------
// Kernel 5: WARP-PER-PIXEL exact top-102 + sparse recon.
// One warp owns one pixel; 64 |cos| keys live in registers per lane.
// Binary search rounds are 64 register compares + one __reduce_add_sync —
// no barriers, no block atomics, no smem in the hot loop (R14 analysis:
// block-wide coordination was the select's dominant cost).
// Rank/sum/gather are warp-local; gather fetches one full 512-B fp16 pool
// row per keep-term with a single coalesced uint4 load per lane.
// ---------------------------------------------------------------------------
#define CAND_MAX 112
#define CAND_ARR 192
#define MAXIT    24

__global__ __launch_bounds__(256, 2) void topk_recon(const float* __restrict__ pool,
                                                     float* __restrict__ out) {
    int lane = threadIdx.x & 31;
    int warp = threadIdx.x >> 5;
    int pixel = blockIdx.x * 8 + warp;          // 0 .. 16383
    int n = pixel >> 10, l = pixel & (LL - 1);
    const float* row = g_cos + (size_t)pixel * PP;
    const float4* row4 = (const float4*)row;

    __shared__ float ckey[8][CAND_ARR];
    __shared__ int   cidx[8][CAND_ARR];
    __shared__ int   s_idx[8][KEEP];
    __shared__ float s_val[8][KEEP];
    __shared__ int   wcnt[8];

    // Load 64 keys per lane (coalesced float4: element idx = i*128+lane*4+c).
    float key[64];
    #pragma unroll
    for (int i = 0; i < 16; i++) {
        float4 v = __ldg(&row4[i * 32 + lane]);
        key[i * 4 + 0] = fabsf(v.x);
        key[i * 4 + 1] = fabsf(v.y);
        key[i * 4 + 2] = fabsf(v.z);
        key[i * 4 + 3] = fabsf(v.w);
    }
    if (lane == 0) wcnt[warp] = 0;
    __syncwarp();

    // Warp-local binary search. Invariant: count(key >= lo) >= KEEP.
    unsigned lo = 0u, hi = 0x3FC00000u;
    int cntLo = PP;
    int it = 0;
    while (cntLo > CAND_MAX && it < MAXIT) {
        unsigned mid = (lo + hi) >> 1;
        float mf = __uint_as_float(mid);
        int c = 0;
        #pragma unroll
        for (int k = 0; k < 64; k++) c += (key[k] >= mf);
        c = __reduce_add_sync(0xFFFFFFFFu, c);
        if (c >= KEEP) { lo = mid; cntLo = c; }
        else           { hi = mid; }
        it++;
    }
    float loF = __uint_as_float(lo);

    // Collect candidates into this warp's smem region.
    #pragma unroll
    for (int i = 0; i < 16; i++) {
        #pragma unroll
        for (int comp = 0; comp < 4; comp++) {
            float kv = key[i * 4 + comp];
            if (kv >= loF) {
                int slot = atomicAdd(&wcnt[warp], 1);
                if (slot < CAND_ARR) {
                    ckey[warp][slot] = kv;
                    cidx[warp][slot] = i * 128 + lane * 4 + comp;
                }
            }
        }
    }
    __syncwarp();
    int C = wcnt[warp];
    if (C > CAND_ARR) C = CAND_ARR;    // safety (unreachable with real data)

    // Exact rank per candidate (inner reads are LDS broadcasts).
    for (int i = lane; i < C; i += 32) {
        float ki = ckey[warp][i];
        int   ii = cidx[warp][i];
        int rank = 0;
        #pragma unroll 4
        for (int j = 0; j < C; j++) {
            float kj = ckey[warp][j];
            int   ij = cidx[warp][j];
            rank += (kj > ki) | ((kj == ki) & (ij < ii));
        }
        if (rank < KEEP) {
            s_idx[warp][rank] = ii;
            s_val[warp][rank] = __ldg(&row[ii]);   // signed value (L1/L2-hot)
        }
    }
    __syncwarp();

    // Deterministic rank-ordered sum (fixed-order shfl tree).
    float v = s_val[warp][lane] + s_val[warp][lane + 32] + s_val[warp][lane + 64]
            + ((lane + 96 < KEEP) ? s_val[warp][lane + 96] : 0.f);
    #pragma unroll
    for (int off = 16; off > 0; off >>= 1)
        v += __shfl_down_sync(0xFFFFFFFFu, v, off);
    float invS = 1.0f / __shfl_sync(0xFFFFFFFFu, v, 0);

    // Gather: per keep-term the warp loads one full fp16 pool row (512 B,
    // uint4 per lane), accumulating 8 channels per lane in registers.
    float acc[8] = {0.f, 0.f, 0.f, 0.f, 0.f, 0.f, 0.f, 0.f};
    #pragma unroll 2
    for (int j = 0; j < KEEP; j++) {
        float w   = s_val[warp][j];       // LDS broadcast
        int   idx = s_idx[warp][j];       // LDS broadcast
        uint4 h = *(const uint4*)(g_pool16 + (size_t)idx * CCH + lane * 8);
        const __half2* hp = (const __half2*)&h;
        float2 f0 = __half22float2(hp[0]);
        float2 f1 = __half22float2(hp[1]);
        float2 f2 = __half22float2(hp[2]);
        float2 f3 = __half22float2(hp[3]);
        acc[0] = fmaf(w, f0.x, acc[0]);
        acc[1] = fmaf(w, f0.y, acc[1]);
        acc[2] = fmaf(w, f1.x, acc[2]);
        acc[3] = fmaf(w, f1.y, acc[3]);
        acc[4] = fmaf(w, f2.x, acc[4]);
        acc[5] = fmaf(w, f2.y, acc[5]);
        acc[6] = fmaf(w, f3.x, acc[6]);
        acc[7] = fmaf(w, f3.y, acc[7]);
    }

    float* outp = out + (size_t)n * CCH * LL + (size_t)(lane * 8) * LL + l;
    #pragma unroll
    for (int c8 = 0; c8 < 8; c8++)
        outp[(size_t)c8 * LL] = acc[c8] * invS;
}

// ---------------------------------------------------------------------------
// Launch
// ---------------------------------------------------------------------------
extern "C" void kernel_launch(void* const* d_in, const int* in_sizes, int n_in,
                              void* d_out, int out_size) {
    const float* x    = (const float*)d_in[0];  // [16, 256, 32, 32]
    const float* pool = (const float*)d_in[1];  // [2048, 256]
    float* out        = (float*)d_out;          // [16, 256, 32, 32]

    cudaFuncSetAttribute(gemm_mma, cudaFuncAttributeMaxDynamicSharedMemorySize, SMEM_GEMM);

    prep_pool<<<PP, 256>>>(pool);
    prep_xnorm<<<(NB * LL) / 256, 256>>>(x);
    prep_xT<<<dim3(LL / 32, CCH / 32, NB), 256>>>(x);
    gemm_mma<<<dim3(PP / 128, LL / 128, NB), 256, SMEM_GEMM>>>();
    topk_recon<<<NB * LL / 8, 256>>>(pool, out);
}